// round 1
// baseline (speedup 1.0000x reference)
#include <cuda_runtime.h>
#include <cuda_bf16.h>
#include <math_constants.h>

// Problem constants
#define BATCH    1024
#define NHID     1024
#define NCLASSES 224
#define NPC      225

// ---------------- scratch (device globals; no allocations allowed) ----------
__device__ float g_top_logits[BATCH * NCLASSES];
__device__ float g_top_p[BATCH];
__device__ int   g_pos_top[BATCH];
__device__ int   g_pos_bottom[BATCH];
__device__ int   g_count[NCLASSES];
__device__ int   g_offset[NCLASSES + 1];
__device__ int   g_fill[NCLASSES];
__device__ int   g_sorted[BATCH];

// ---------------- 0: init counters ------------------------------------------
__global__ void k_init() {
    int t = threadIdx.x;
    if (t < NCLASSES) { g_count[t] = 0; g_fill[t] = 0; }
}

// ---------------- 1: decode labels (int32 or int64), histogram --------------
__global__ void k_decode(const void* __restrict__ labels_raw) {
    // Detect int64 vs int32: for int64 little-endian non-negative labels,
    // every odd 32-bit word is zero. For int32 random labels that's ~impossible.
    const unsigned int* w = (const unsigned int*)labels_raw;
    bool is64 = ((w[1] | w[3] | w[5] | w[7] | w[9] | w[11] | w[13] | w[15]) == 0u);

    int s = blockIdx.x * blockDim.x + threadIdx.x;
    if (s >= BATCH) return;
    long long lab;
    if (is64) lab = ((const long long*)labels_raw)[s];
    else      lab = (long long)(((const int*)labels_raw)[s]);
    int pt = (int)(lab / NPC);
    int pb = (int)(lab % NPC);
    g_pos_top[s]    = pt;
    g_pos_bottom[s] = pb;
    atomicAdd(&g_count[pt], 1);
}

// ---------------- 2: serial exclusive scan over 224 classes -----------------
__global__ void k_scan() {
    int acc = 0;
    for (int c = 0; c < NCLASSES; c++) { g_offset[c] = acc; acc += g_count[c]; }
    g_offset[NCLASSES] = acc;
}

// ---------------- 3: scatter sample ids into class-sorted order -------------
__global__ void k_scatter() {
    int s = blockIdx.x * blockDim.x + threadIdx.x;
    if (s >= BATCH) return;
    int c = g_pos_top[s];
    int p = atomicAdd(&g_fill[c], 1);
    g_sorted[g_offset[c] + p] = s;
}

// ---------------- 4: top GEMM: logits[B,224] = X @ Wt + bt ------------------
// grid 128 blocks, BM=8 rows per block, 256 threads, K chunked by 32.
__global__ void __launch_bounds__(256) k_top_gemm(
    const float* __restrict__ X,
    const float* __restrict__ Wt,   // [NHID, NCLASSES], row-major (d*224 + c)
    const float* __restrict__ bt)
{
    int r0   = blockIdx.x * 8;
    int t    = threadIdx.x;
    int row  = t >> 5;      // 0..7
    int lane = t & 31;      // 0..31

    __shared__ float Xs[8][32];
    __shared__ float Ws[32][NCLASSES];

    float acc[7];
#pragma unroll
    for (int i = 0; i < 7; i++) acc[i] = 0.f;

    for (int k0 = 0; k0 < NHID; k0 += 32) {
        __syncthreads();
        Xs[row][lane] = X[(r0 + row) * NHID + k0 + lane];
#pragma unroll
        for (int i = t; i < 32 * NCLASSES; i += 256) {
            int kk = i / NCLASSES;
            int c  = i - kk * NCLASSES;
            Ws[kk][c] = Wt[(k0 + kk) * NCLASSES + c];
        }
        __syncthreads();
#pragma unroll
        for (int kk = 0; kk < 32; kk++) {
            float a = Xs[row][kk];
#pragma unroll
            for (int i = 0; i < 7; i++)
                acc[i] += a * Ws[kk][lane + 32 * i];
        }
    }
#pragma unroll
    for (int i = 0; i < 7; i++) {
        int c = lane + 32 * i;
        g_top_logits[(r0 + row) * NCLASSES + c] = acc[i] + bt[c];
    }
}

// ---------------- 5: top softmax -> target-class probability ----------------
// one warp per sample; 224 = 7 * 32
__global__ void __launch_bounds__(256) k_top_softmax() {
    int wid  = (blockIdx.x * blockDim.x + threadIdx.x) >> 5;
    int lane = threadIdx.x & 31;
    if (wid >= BATCH) return;
    const float* L = g_top_logits + wid * NCLASSES;

    float l[7];
    float mx = -CUDART_INF_F;
#pragma unroll
    for (int i = 0; i < 7; i++) {
        l[i] = L[lane + 32 * i];
        mx = fmaxf(mx, l[i]);
    }
#pragma unroll
    for (int o = 16; o > 0; o >>= 1) mx = fmaxf(mx, __shfl_xor_sync(0xFFFFFFFFu, mx, o));

    float s = 0.f;
#pragma unroll
    for (int i = 0; i < 7; i++) s += __expf(l[i] - mx);
#pragma unroll
    for (int o = 16; o > 0; o >>= 1) s += __shfl_xor_sync(0xFFFFFFFFu, s, o);

    if (lane == 0) {
        int tc = g_pos_top[wid];
        g_top_p[wid] = __expf(L[tc] - mx) / s;
    }
}

// ---------------- 6: bottom (grouped by class) + softmax + final out --------
// one block per class; chunks of up to 6 samples held in smem; thread j owns
// bottom column j (j < 225); weight slice streamed once per chunk, coalesced.
#define SCHUNK 6
__global__ void __launch_bounds__(256) k_bottom(
    const float* __restrict__ X,
    const float* __restrict__ Wb,   // [NCLASSES, NHID, NPC]
    const float* __restrict__ bb,   // [NCLASSES, NPC]
    float* __restrict__ out)
{
    int c = blockIdx.x;
    int n = g_count[c];
    if (n == 0) return;
    int base = g_offset[c];
    int t = threadIdx.x;

    __shared__ float Xs[SCHUNK][NHID];
    __shared__ float red[256];
    __shared__ int   s_ids[SCHUNK];

    const float* W = Wb + (size_t)c * NHID * NPC;
    float bias = (t < NPC) ? bb[c * NPC + t] : 0.f;

    for (int s0 = 0; s0 < n; s0 += SCHUNK) {
        int ns = min(SCHUNK, n - s0);
        if (t < ns) s_ids[t] = g_sorted[base + s0 + t];
        __syncthreads();

        // stage the chunk's input rows
        for (int s = 0; s < ns; s++) {
            int sid = s_ids[s];
            const float* xr = X + (size_t)sid * NHID;
            for (int d = t; d < NHID; d += 256) Xs[s][d] = xr[d];
        }
        __syncthreads();

        float acc[SCHUNK];
#pragma unroll
        for (int s = 0; s < SCHUNK; s++) acc[s] = 0.f;

        if (t < NPC) {
            const float* Wj = W + t;
#pragma unroll 4
            for (int d = 0; d < NHID; d++) {
                float w = Wj[(size_t)d * NPC];
#pragma unroll
                for (int s = 0; s < SCHUNK; s++)
                    acc[s] += Xs[s][d] * w;     // lanes beyond ns: dead work
            }
        }

        // per-sample block softmax over the 225 columns
        for (int s = 0; s < ns; s++) {
            float v = (t < NPC) ? (acc[s] + bias) : -CUDART_INF_F;
            red[t] = v; __syncthreads();
#pragma unroll
            for (int off = 128; off > 0; off >>= 1) {
                if (t < off) red[t] = fmaxf(red[t], red[t + off]);
                __syncthreads();
            }
            float mx = red[0]; __syncthreads();

            float e = (t < NPC) ? __expf(v - mx) : 0.f;
            red[t] = e; __syncthreads();
#pragma unroll
            for (int off = 128; off > 0; off >>= 1) {
                if (t < off) red[t] += red[t + off];
                __syncthreads();
            }
            float sum = red[0]; __syncthreads();

            int sid = s_ids[s];
            if (t == g_pos_bottom[sid])
                out[sid] = g_top_p[sid] * (e / sum);
        }
        __syncthreads();
    }
}

// ---------------- launch ------------------------------------------------------
extern "C" void kernel_launch(void* const* d_in, const int* in_sizes, int n_in,
                              void* d_out, int out_size)
{
    const float* X   = (const float*)d_in[0];   // [1024, 1024]
    const void*  lab = d_in[1];                 // [1024] int32 or int64
    const float* Wt  = (const float*)d_in[2];   // [1024, 224]
    const float* bt  = (const float*)d_in[3];   // [224]
    const float* Wb  = (const float*)d_in[4];   // [224, 1024, 225]
    const float* bb  = (const float*)d_in[5];   // [224, 225]
    float* out = (float*)d_out;                 // [1024]

    k_init<<<1, 256>>>();
    k_decode<<<4, 256>>>(lab);
    k_scan<<<1, 1>>>();
    k_scatter<<<4, 256>>>();
    k_top_gemm<<<128, 256>>>(X, Wt, bt);
    k_top_softmax<<<128, 256>>>();
    k_bottom<<<NCLASSES, 256>>>(X, Wb, bb, out);
}

// round 2
// speedup vs baseline: 3.0759x; 3.0759x over previous
#include <cuda_runtime.h>
#include <cuda_bf16.h>
#include <math_constants.h>

#define BATCH    1024
#define NHID     1024
#define NCLASSES 224
#define NPC      225
#define NPAD     232
#define DSEG     8
#define DLEN     128      // NHID / DSEG
#define SCH      8        // samples per chunk (bottom)

// ---------------- scratch (device globals) ----------------------------------
__device__ float g_top_logits[BATCH * NCLASSES];
__device__ float g_top_p[BATCH];
__device__ int   g_pos_top[BATCH];
__device__ int   g_pos_bottom[BATCH];
__device__ int   g_count[NCLASSES];
__device__ int   g_offset[NCLASSES + 1];
__device__ int   g_sorted[BATCH];
__device__ float g_bot_part[DSEG][BATCH][NPAD];

// ---------------- 1: prep — decode labels, histogram, scan, scatter, zero ---
__global__ void __launch_bounds__(1024) k_prep(const void* __restrict__ labels_raw)
{
    __shared__ int s_count[NCLASSES];
    __shared__ int s_off[NCLASSES];
    int t = threadIdx.x;   // 1024 threads, one per sample

    if (t < NCLASSES) s_count[t] = 0;
    __syncthreads();

    // detect int64 vs int32 labels (odd 32-bit words all zero => int64 LE)
    const unsigned int* w = (const unsigned int*)labels_raw;
    bool is64 = ((w[1] | w[3] | w[5] | w[7] | w[9] | w[11] | w[13] | w[15]) == 0u);
    long long lab = is64 ? ((const long long*)labels_raw)[t]
                         : (long long)(((const int*)labels_raw)[t]);
    int pt = (int)(lab / NPC);
    int pb = (int)(lab % NPC);
    g_pos_top[t]    = pt;
    g_pos_bottom[t] = pb;
    atomicAdd(&s_count[pt], 1);
    __syncthreads();

    // warp 0: exclusive scan of 224 counts (7 per lane + shuffle scan)
    if (t < 32) {
        int base = t * 7;
        int v[7], loc[7];
        int sum = 0;
#pragma unroll
        for (int i = 0; i < 7; i++) { v[i] = s_count[base + i]; }
#pragma unroll
        for (int i = 0; i < 7; i++) { loc[i] = sum; sum += v[i]; }
        int run = sum;
#pragma unroll
        for (int o = 1; o < 32; o <<= 1) {
            int nb = __shfl_up_sync(0xFFFFFFFFu, run, o);
            if (t >= o) run += nb;
        }
        int excl = run - sum;
#pragma unroll
        for (int i = 0; i < 7; i++) {
            s_off[base + i]    = excl + loc[i];
            g_offset[base + i] = excl + loc[i];
        }
        if (t == 31) g_offset[NCLASSES] = excl + sum;
    }
    __syncthreads();
    if (t < NCLASSES) g_count[t] = s_count[t];

    // scatter into class-sorted order
    int p = atomicAdd(&s_off[pt], 1);
    g_sorted[p] = t;

    // zero the top-logit accumulator (atomics accumulate into it each call)
#pragma unroll 4
    for (int i = t; i < BATCH * NCLASSES; i += 1024) g_top_logits[i] = 0.f;
}

// ---------------- 2: top GEMM (split-K, register-tiled) ---------------------
// grid (16 rowgroups, 8 ksegs); block 256 = 8 warps; warp owns 8 rows x 7 cols.
__global__ void __launch_bounds__(256) k_top(
    const float* __restrict__ X,
    const float* __restrict__ Wt)    // [NHID, NCLASSES]
{
    int r0 = blockIdx.x * 64;
    int k0 = blockIdx.y * 128;
    int t = threadIdx.x, warp = t >> 5, lane = t & 31;

    __shared__ float Xs[64][128];          // 32 KB
    __shared__ float Ws[16][NCLASSES];     // 14.3 KB

    // stage X tile (64 rows x 128 k), float4 coalesced
    for (int i = t; i < 64 * 32; i += 256) {
        int r = i >> 5, q = i & 31;
        const float4* src = (const float4*)(X + (size_t)(r0 + r) * NHID + k0);
        ((float4*)&Xs[r][0])[q] = src[q];
    }

    float acc[8][7];
#pragma unroll
    for (int r = 0; r < 8; r++)
#pragma unroll
        for (int i = 0; i < 7; i++) acc[r][i] = 0.f;

    for (int kc = 0; kc < 128; kc += 16) {
        __syncthreads();
        for (int i = t; i < 16 * NCLASSES; i += 256) {
            int kk = i / NCLASSES;
            int c  = i - kk * NCLASSES;
            Ws[kk][c] = Wt[(size_t)(k0 + kc + kk) * NCLASSES + c];
        }
        __syncthreads();
#pragma unroll 4
        for (int kk = 0; kk < 16; kk++) {
            float xv[8];
#pragma unroll
            for (int r = 0; r < 8; r++) xv[r] = Xs[warp * 8 + r][kc + kk];
#pragma unroll
            for (int i = 0; i < 7; i++) {
                float wv = Ws[kk][lane + 32 * i];
#pragma unroll
                for (int r = 0; r < 8; r++) acc[r][i] += xv[r] * wv;
            }
        }
    }

#pragma unroll
    for (int r = 0; r < 8; r++) {
        int row = r0 + warp * 8 + r;
#pragma unroll
        for (int i = 0; i < 7; i++)
            atomicAdd(&g_top_logits[row * NCLASSES + lane + 32 * i], acc[r][i]);
    }
}

// ---------------- 3: top softmax -> target-class probability ----------------
__global__ void __launch_bounds__(256) k_top_softmax(const float* __restrict__ bt)
{
    int wid  = (blockIdx.x * blockDim.x + threadIdx.x) >> 5;
    int lane = threadIdx.x & 31;
    if (wid >= BATCH) return;
    const float* L = g_top_logits + wid * NCLASSES;

    float l[7];
    float mx = -CUDART_INF_F;
#pragma unroll
    for (int i = 0; i < 7; i++) {
        int c = lane + 32 * i;
        l[i] = L[c] + bt[c];
        mx = fmaxf(mx, l[i]);
    }
#pragma unroll
    for (int o = 16; o > 0; o >>= 1) mx = fmaxf(mx, __shfl_xor_sync(0xFFFFFFFFu, mx, o));

    float s = 0.f;
#pragma unroll
    for (int i = 0; i < 7; i++) s += __expf(l[i] - mx);
#pragma unroll
    for (int o = 16; o > 0; o >>= 1) s += __shfl_xor_sync(0xFFFFFFFFu, s, o);

    if (lane == 0) {
        int tc = g_pos_top[wid];
        g_top_p[wid] = __expf(L[tc] + bt[tc] - mx) / s;
    }
}

// ---------------- 4: bottom split-D partial dots -----------------------------
// grid (224 classes, 8 d-segments); block 256; thread t<225 owns column t.
__global__ void __launch_bounds__(256) k_bottom_split(
    const float* __restrict__ X,
    const float* __restrict__ Wb)    // [NCLASSES, NHID, NPC]
{
    int c   = blockIdx.x;
    int seg = blockIdx.y;
    int n = g_count[c];
    if (n == 0) return;
    int base = g_offset[c];
    int d0   = seg * DLEN;
    int t = threadIdx.x;

    __shared__ float Xs[SCH][DLEN];
    __shared__ int   ids[SCH];

    const float* W = Wb + (size_t)c * NHID * NPC + (size_t)d0 * NPC;

    for (int s0 = 0; s0 < n; s0 += SCH) {
        int ns = min(SCH, n - s0);
        __syncthreads();
        if (t < ns) ids[t] = g_sorted[base + s0 + t];
        __syncthreads();

        for (int i = t; i < ns * DLEN; i += 256) {
            int s = i >> 7, d = i & (DLEN - 1);
            Xs[s][d] = X[(size_t)ids[s] * NHID + d0 + d];
        }
        __syncthreads();

        if (t < NPC) {
            float acc[SCH];
#pragma unroll
            for (int s = 0; s < SCH; s++) acc[s] = 0.f;
            const float* Wj = W + t;
#pragma unroll 4
            for (int d = 0; d < DLEN; d++) {
                float wv = Wj[(size_t)d * NPC];
#pragma unroll
                for (int s = 0; s < SCH; s++) acc[s] += Xs[s][d] * wv;
            }
            for (int s = 0; s < ns; s++)
                g_bot_part[seg][ids[s]][t] = acc[s];
        }
    }
}

// ---------------- 5: finish — reduce partials, softmax, output --------------
__global__ void __launch_bounds__(256) k_finish(
    const float* __restrict__ bb,   // [NCLASSES, NPC]
    float* __restrict__ out)
{
    int sid = blockIdx.x;
    int t = threadIdx.x;
    int c = g_pos_top[sid];

    __shared__ float red[256];

    float v;
    if (t < NPC) {
        float a = bb[c * NPC + t];
#pragma unroll
        for (int g = 0; g < DSEG; g++) a += g_bot_part[g][sid][t];
        v = a;
    } else {
        v = -CUDART_INF_F;
    }

    red[t] = v; __syncthreads();
#pragma unroll
    for (int off = 128; off > 0; off >>= 1) {
        if (t < off) red[t] = fmaxf(red[t], red[t + off]);
        __syncthreads();
    }
    float mx = red[0]; __syncthreads();

    float e = (t < NPC) ? __expf(v - mx) : 0.f;
    red[t] = e; __syncthreads();
#pragma unroll
    for (int off = 128; off > 0; off >>= 1) {
        if (t < off) red[t] += red[t + off];
        __syncthreads();
    }
    float sum = red[0];

    if (t == g_pos_bottom[sid])
        out[sid] = g_top_p[sid] * (e / sum);
}

// ---------------- launch -----------------------------------------------------
extern "C" void kernel_launch(void* const* d_in, const int* in_sizes, int n_in,
                              void* d_out, int out_size)
{
    const float* X   = (const float*)d_in[0];   // [1024, 1024]
    const void*  lab = d_in[1];                 // [1024] int32/int64
    const float* Wt  = (const float*)d_in[2];   // [1024, 224]
    const float* bt  = (const float*)d_in[3];   // [224]
    const float* Wb  = (const float*)d_in[4];   // [224, 1024, 225]
    const float* bb  = (const float*)d_in[5];   // [224, 225]
    float* out = (float*)d_out;

    k_prep<<<1, 1024>>>(lab);
    k_top<<<dim3(16, 8), 256>>>(X, Wt);
    k_top_softmax<<<128, 256>>>(bt);
    k_bottom_split<<<dim3(NCLASSES, DSEG), 256>>>(X, Wb);
    k_finish<<<BATCH, 256>>>(bb, out);
}

// round 3
// speedup vs baseline: 3.1356x; 1.0194x over previous
#include <cuda_runtime.h>
#include <cuda_bf16.h>
#include <math_constants.h>

#define BATCH    1024
#define NHID     1024
#define NCLASSES 224
#define NPC      225
#define NPAD     232
#define DSEG     8
#define DLEN     128      // NHID / DSEG
#define SCH      8        // samples per chunk (bottom)
#define KSEG     8        // split-K for top gemm
#define KLEN     128      // NHID / KSEG
#define TROWS    32       // rows per top-gemm block

// ---------------- scratch (device globals) ----------------------------------
__device__ float g_top_part[KSEG][BATCH][NCLASSES];
__device__ int   g_pos_top[BATCH];
__device__ int   g_pos_bottom[BATCH];
__device__ int   g_count[NCLASSES];
__device__ int   g_offset[NCLASSES + 1];
__device__ int   g_sorted[BATCH];
__device__ float g_bot_part[DSEG][BATCH][NPAD];

// ---------------- 1: prep — decode labels, histogram, scan, scatter ---------
__global__ void __launch_bounds__(1024) k_prep(const void* __restrict__ labels_raw)
{
    __shared__ int s_count[NCLASSES];
    __shared__ int s_off[NCLASSES];
    int t = threadIdx.x;   // 1024 threads, one per sample

    if (t < NCLASSES) s_count[t] = 0;
    __syncthreads();

    // detect int64 vs int32 labels (odd 32-bit words all zero => int64 LE)
    const unsigned int* w = (const unsigned int*)labels_raw;
    bool is64 = ((w[1] | w[3] | w[5] | w[7] | w[9] | w[11] | w[13] | w[15]) == 0u);
    long long lab = is64 ? ((const long long*)labels_raw)[t]
                         : (long long)(((const int*)labels_raw)[t]);
    int pt = (int)(lab / NPC);
    int pb = (int)(lab % NPC);
    g_pos_top[t]    = pt;
    g_pos_bottom[t] = pb;
    atomicAdd(&s_count[pt], 1);
    __syncthreads();

    // warp 0: exclusive scan of 224 counts (7 per lane + shuffle scan)
    if (t < 32) {
        int base = t * 7;
        int v[7], loc[7];
        int sum = 0;
#pragma unroll
        for (int i = 0; i < 7; i++) { v[i] = s_count[base + i]; }
#pragma unroll
        for (int i = 0; i < 7; i++) { loc[i] = sum; sum += v[i]; }
        int run = sum;
#pragma unroll
        for (int o = 1; o < 32; o <<= 1) {
            int nb = __shfl_up_sync(0xFFFFFFFFu, run, o);
            if (t >= o) run += nb;
        }
        int excl = run - sum;
#pragma unroll
        for (int i = 0; i < 7; i++) {
            s_off[base + i]    = excl + loc[i];
            g_offset[base + i] = excl + loc[i];
        }
        if (t == 31) g_offset[NCLASSES] = excl + sum;
    }
    __syncthreads();
    if (t < NCLASSES) g_count[t] = s_count[t];

    // scatter into class-sorted order
    int p = atomicAdd(&s_off[pt], 1);
    g_sorted[p] = t;
}

// ---------------- 2: top GEMM (split-K, partials, no atomics) ----------------
// grid (32 rowgroups, 8 ksegs); block 256 = 8 warps; warp owns 4 rows x 7 cols.
__global__ void __launch_bounds__(256) k_top(
    const float* __restrict__ X,
    const float* __restrict__ Wt)    // [NHID, NCLASSES]
{
    int r0 = blockIdx.x * TROWS;
    int k0 = blockIdx.y * KLEN;
    int t = threadIdx.x, warp = t >> 5, lane = t & 31;

    __shared__ float Xs[TROWS][KLEN];      // 16 KB
    __shared__ float Ws[16][NCLASSES];     // 14.3 KB

    // stage X tile (32 rows x 128 k), float4 coalesced
    for (int i = t; i < TROWS * 32; i += 256) {
        int r = i >> 5, q = i & 31;
        const float4* src = (const float4*)(X + (size_t)(r0 + r) * NHID + k0);
        ((float4*)&Xs[r][0])[q] = src[q];
    }

    float acc[4][7];
#pragma unroll
    for (int r = 0; r < 4; r++)
#pragma unroll
        for (int i = 0; i < 7; i++) acc[r][i] = 0.f;

    for (int kc = 0; kc < KLEN; kc += 16) {
        __syncthreads();
        for (int i = t; i < 16 * NCLASSES; i += 256) {
            int kk = i / NCLASSES;
            int c  = i - kk * NCLASSES;
            Ws[kk][c] = Wt[(size_t)(k0 + kc + kk) * NCLASSES + c];
        }
        __syncthreads();
#pragma unroll 4
        for (int kk = 0; kk < 16; kk++) {
            float xv[4];
#pragma unroll
            for (int r = 0; r < 4; r++) xv[r] = Xs[warp * 4 + r][kc + kk];
#pragma unroll
            for (int i = 0; i < 7; i++) {
                float wv = Ws[kk][lane + 32 * i];
#pragma unroll
                for (int r = 0; r < 4; r++) acc[r][i] += xv[r] * wv;
            }
        }
    }

#pragma unroll
    for (int r = 0; r < 4; r++) {
        int row = r0 + warp * 4 + r;
#pragma unroll
        for (int i = 0; i < 7; i++)
            g_top_part[blockIdx.y][row][lane + 32 * i] = acc[r][i];
    }
}

// ---------------- 3: bottom split-D partial dots -----------------------------
// grid (224 classes, 8 d-segments); block 256; thread t<225 owns column t.
__global__ void __launch_bounds__(256) k_bottom_split(
    const float* __restrict__ X,
    const float* __restrict__ Wb)    // [NCLASSES, NHID, NPC]
{
    int c   = blockIdx.x;
    int seg = blockIdx.y;
    int n = g_count[c];
    if (n == 0) return;
    int base = g_offset[c];
    int d0   = seg * DLEN;
    int t = threadIdx.x;

    __shared__ float Xs[SCH][DLEN];
    __shared__ int   ids[SCH];

    const float* W = Wb + (size_t)c * NHID * NPC + (size_t)d0 * NPC;

    for (int s0 = 0; s0 < n; s0 += SCH) {
        int ns = min(SCH, n - s0);
        __syncthreads();
        if (t < ns) ids[t] = g_sorted[base + s0 + t];
        __syncthreads();

        // stage X rows (float4 coalesced; d0*4 bytes is 512B aligned)
        for (int i = t; i < ns * 32; i += 256) {
            int s = i >> 5, q = i & 31;
            const float4* src = (const float4*)(X + (size_t)ids[s] * NHID + d0);
            ((float4*)&Xs[s][0])[q] = src[q];
        }
        __syncthreads();

        if (t < NPC) {
            float acc[SCH];
#pragma unroll
            for (int s = 0; s < SCH; s++) acc[s] = 0.f;
            const float* Wj = W + t;
            // unroll-8 with all 8 weight loads issued before the FMA chain
            for (int d = 0; d < DLEN; d += 8) {
                float wr[8];
#pragma unroll
                for (int k = 0; k < 8; k++)
                    wr[k] = __ldg(Wj + (size_t)(d + k) * NPC);
#pragma unroll
                for (int k = 0; k < 8; k++) {
                    float wv = wr[k];
#pragma unroll
                    for (int s = 0; s < SCH; s++)
                        acc[s] += Xs[s][d + k] * wv;
                }
            }
            for (int s = 0; s < ns; s++)
                g_bot_part[seg][ids[s]][t] = acc[s];
        }
    }
}

// ---------------- 4: fused finish — top softmax + bottom softmax + output ---
// one warp per sample; grid 128 x 256
__global__ void __launch_bounds__(256) k_finish(
    const float* __restrict__ bt,   // [224]
    const float* __restrict__ bb,   // [NCLASSES, NPC]
    float* __restrict__ out)
{
    int sid  = (blockIdx.x * blockDim.x + threadIdx.x) >> 5;
    int lane = threadIdx.x & 31;
    if (sid >= BATCH) return;
    int c = g_pos_top[sid];

    // ---- top softmax over 224 classes (7 per lane) ----
    float lt[7];
    float mx = -CUDART_INF_F;
#pragma unroll
    for (int i = 0; i < 7; i++) {
        int cc = lane + 32 * i;
        float a = bt[cc];
#pragma unroll
        for (int g = 0; g < KSEG; g++) a += g_top_part[g][sid][cc];
        lt[i] = a;
        mx = fmaxf(mx, a);
    }
#pragma unroll
    for (int o = 16; o > 0; o >>= 1) mx = fmaxf(mx, __shfl_xor_sync(0xFFFFFFFFu, mx, o));
    float s = 0.f;
#pragma unroll
    for (int i = 0; i < 7; i++) s += __expf(lt[i] - mx);
#pragma unroll
    for (int o = 16; o > 0; o >>= 1) s += __shfl_xor_sync(0xFFFFFFFFu, s, o);

    // target class prob: lane (c&31) holds lt[c>>5]
    float myv  = lt[c >> 5];                    // valid only on lane c&31
    float tgt  = __shfl_sync(0xFFFFFFFFu, myv, c & 31);
    float top_p = __expf(tgt - mx) / s;

    // ---- bottom softmax over 225 columns (8 per lane, last partial) ----
    float vb[8];
    float mxb = -CUDART_INF_F;
#pragma unroll
    for (int k = 0; k < 8; k++) {
        int col = lane + 32 * k;
        if (col < NPC) {
            float a = bb[c * NPC + col];
#pragma unroll
            for (int g = 0; g < DSEG; g++) a += g_bot_part[g][sid][col];
            vb[k] = a;
            mxb = fmaxf(mxb, a);
        } else vb[k] = -CUDART_INF_F;
    }
#pragma unroll
    for (int o = 16; o > 0; o >>= 1) mxb = fmaxf(mxb, __shfl_xor_sync(0xFFFFFFFFu, mxb, o));
    float sb = 0.f;
#pragma unroll
    for (int k = 0; k < 8; k++) sb += __expf(vb[k] - mxb);
#pragma unroll
    for (int o = 16; o > 0; o >>= 1) sb += __shfl_xor_sync(0xFFFFFFFFu, sb, o);

    int pb = g_pos_bottom[sid];
    if (lane == (pb & 31))
        out[sid] = top_p * (__expf(vb[pb >> 5] - mxb) / sb);
}

// ---------------- launch -----------------------------------------------------
extern "C" void kernel_launch(void* const* d_in, const int* in_sizes, int n_in,
                              void* d_out, int out_size)
{
    const float* X   = (const float*)d_in[0];   // [1024, 1024]
    const void*  lab = d_in[1];                 // [1024] int32/int64
    const float* Wt  = (const float*)d_in[2];   // [1024, 224]
    const float* bt  = (const float*)d_in[3];   // [224]
    const float* Wb  = (const float*)d_in[4];   // [224, 1024, 225]
    const float* bb  = (const float*)d_in[5];   // [224, 225]
    float* out = (float*)d_out;

    k_prep<<<1, 1024>>>(lab);
    k_top<<<dim3(BATCH / TROWS, KSEG), 256>>>(X, Wt);
    k_bottom_split<<<dim3(NCLASSES, DSEG), 256>>>(X, Wb);
    k_finish<<<BATCH / 8, 256>>>(bt, bb, out);
}

// round 4
// speedup vs baseline: 3.7958x; 1.2105x over previous
#include <cuda_runtime.h>
#include <cuda_bf16.h>
#include <math_constants.h>

#define BATCH    1024
#define NHID     1024
#define NCLASSES 224
#define NPC      225
#define DSEG     8
#define DLEN     128      // NHID / DSEG
#define SCH      8        // samples per chunk (bottom)
#define KSEG     8        // split-K for top gemm
#define KLEN     128      // NHID / KSEG
#define TROWS    64       // rows per top-gemm block (8 warps x 8 rows)

// ---------------- scratch (device globals) ----------------------------------
__device__ float g_top_logits[BATCH * NCLASSES];
__device__ float g_bot_logits[BATCH * NPC];
__device__ int   g_pos_top[BATCH];
__device__ int   g_pos_bottom[BATCH];
__device__ int   g_count[NCLASSES];
__device__ int   g_offset[NCLASSES + 1];
__device__ int   g_sorted[BATCH];

// ---------------- 0: zero logit accumulators ---------------------------------
__global__ void __launch_bounds__(256) k_zero()
{
    int i = blockIdx.x * blockDim.x + threadIdx.x;
    int N1 = BATCH * NCLASSES;          // 229376
    int N2 = BATCH * NPC;               // 230400
    int stride = gridDim.x * blockDim.x;
    for (int j = i; j < N1; j += stride) g_top_logits[j] = 0.f;
    for (int j = i; j < N2; j += stride) g_bot_logits[j] = 0.f;
}

// ---------------- 1: prep — decode labels, histogram, scan, scatter ---------
__global__ void __launch_bounds__(1024) k_prep(const void* __restrict__ labels_raw)
{
    __shared__ int s_count[NCLASSES];
    __shared__ int s_off[NCLASSES];
    int t = threadIdx.x;   // 1024 threads, one per sample

    if (t < NCLASSES) s_count[t] = 0;
    __syncthreads();

    // detect int64 vs int32 labels (odd 32-bit words all zero => int64 LE)
    const unsigned int* w = (const unsigned int*)labels_raw;
    bool is64 = ((w[1] | w[3] | w[5] | w[7] | w[9] | w[11] | w[13] | w[15]) == 0u);
    long long lab = is64 ? ((const long long*)labels_raw)[t]
                         : (long long)(((const int*)labels_raw)[t]);
    int pt = (int)(lab / NPC);
    int pb = (int)(lab % NPC);
    g_pos_top[t]    = pt;
    g_pos_bottom[t] = pb;
    atomicAdd(&s_count[pt], 1);
    __syncthreads();

    // warp 0: exclusive scan of 224 counts
    if (t < 32) {
        int base = t * 7;
        int v[7], loc[7];
        int sum = 0;
#pragma unroll
        for (int i = 0; i < 7; i++) v[i] = s_count[base + i];
#pragma unroll
        for (int i = 0; i < 7; i++) { loc[i] = sum; sum += v[i]; }
        int run = sum;
#pragma unroll
        for (int o = 1; o < 32; o <<= 1) {
            int nb = __shfl_up_sync(0xFFFFFFFFu, run, o);
            if (t >= o) run += nb;
        }
        int excl = run - sum;
#pragma unroll
        for (int i = 0; i < 7; i++) {
            s_off[base + i]    = excl + loc[i];
            g_offset[base + i] = excl + loc[i];
        }
        if (t == 31) g_offset[NCLASSES] = excl + sum;
    }
    __syncthreads();
    if (t < NCLASSES) g_count[t] = s_count[t];

    int p = atomicAdd(&s_off[pt], 1);
    g_sorted[p] = t;
}

// ---------------- 2: top GEMM (split-K, atomic epilogue) ----------------------
// grid (16 rowgroups, 8 ksegs) = 128 blocks (one wave); 8 warps x 8 rows each.
__global__ void __launch_bounds__(256) k_top(
    const float* __restrict__ X,
    const float* __restrict__ Wt)    // [NHID, NCLASSES]
{
    int r0 = blockIdx.x * TROWS;
    int k0 = blockIdx.y * KLEN;
    int t = threadIdx.x, warp = t >> 5, lane = t & 31;

    __shared__ float Xs[TROWS][KLEN];      // 32 KB
    __shared__ float Ws[16][NCLASSES];     // 14.3 KB

    // stage X tile (64 rows x 128 k), float4 coalesced
    for (int i = t; i < TROWS * 32; i += 256) {
        int r = i >> 5, q = i & 31;
        const float4* src = (const float4*)(X + (size_t)(r0 + r) * NHID + k0);
        ((float4*)&Xs[r][0])[q] = src[q];
    }

    float acc[8][7];
#pragma unroll
    for (int r = 0; r < 8; r++)
#pragma unroll
        for (int i = 0; i < 7; i++) acc[r][i] = 0.f;

    for (int kc = 0; kc < KLEN; kc += 16) {
        __syncthreads();
        for (int i = t; i < 16 * NCLASSES; i += 256) {
            int kk = i / NCLASSES;
            int c  = i - kk * NCLASSES;
            Ws[kk][c] = Wt[(size_t)(k0 + kc + kk) * NCLASSES + c];
        }
        __syncthreads();
#pragma unroll
        for (int kq = 0; kq < 16; kq += 4) {
            // broadcast X values via LDS.128 (4 k per wavefront per row)
            float4 xv[8];
#pragma unroll
            for (int r = 0; r < 8; r++)
                xv[r] = *(const float4*)&Xs[warp * 8 + r][kc + kq];
            const float* xf = (const float*)xv;
#pragma unroll
            for (int j = 0; j < 4; j++) {
#pragma unroll
                for (int i = 0; i < 7; i++) {
                    float wv = Ws[kq + j][lane + 32 * i];
#pragma unroll
                    for (int r = 0; r < 8; r++)
                        acc[r][i] += xf[r * 4 + j] * wv;
                }
            }
        }
    }

#pragma unroll
    for (int r = 0; r < 8; r++) {
        int row = r0 + warp * 8 + r;
#pragma unroll
        for (int i = 0; i < 7; i++)
            atomicAdd(&g_top_logits[row * NCLASSES + lane + 32 * i], acc[r][i]);
    }
}

// ---------------- 3: bottom split-D (2 cols/thread, LDS.128 X) ---------------
// grid (224 classes, 8 d-segments); block 128 = 4 warps; warp w covers cols
// [64w, 64w+64): lane l owns cols 64w+l and 64w+32+l.
__global__ void __launch_bounds__(128) k_bottom(
    const float* __restrict__ X,
    const float* __restrict__ Wb)    // [NCLASSES, NHID, NPC]
{
    int c   = blockIdx.x;
    int seg = blockIdx.y;
    int n = g_count[c];
    if (n == 0) return;
    int base = g_offset[c];
    int d0   = seg * DLEN;
    int t = threadIdx.x, warp = t >> 5, lane = t & 31;

    int c0 = warp * 64 + lane;
    int c1 = c0 + 32;
    bool v0 = (c0 < NPC), v1 = (c1 < NPC);

    __shared__ float Xs[SCH][DLEN];    // 4 KB
    __shared__ int   ids[SCH];

    const float* W = Wb + (size_t)c * NHID * NPC + (size_t)d0 * NPC;

    for (int s0 = 0; s0 < n; s0 += SCH) {
        int ns = min(SCH, n - s0);
        __syncthreads();
        if (t < ns) ids[t] = g_sorted[base + s0 + t];
        __syncthreads();

        // stage X rows (float4 coalesced), zero-fill unused sample slots
        for (int i = t; i < SCH * 32; i += 128) {
            int s = i >> 5, q = i & 31;
            float4 val = make_float4(0.f, 0.f, 0.f, 0.f);
            if (s < ns)
                val = ((const float4*)(X + (size_t)ids[s] * NHID + d0))[q];
            ((float4*)&Xs[s][0])[q] = val;
        }
        __syncthreads();

        float acc0[SCH], acc1[SCH];
#pragma unroll
        for (int s = 0; s < SCH; s++) { acc0[s] = 0.f; acc1[s] = 0.f; }

#pragma unroll 2
        for (int dq = 0; dq < DLEN; dq += 4) {
            float w0[4], w1[4];
            const float* Wd = W + (size_t)dq * NPC;
#pragma unroll
            for (int k = 0; k < 4; k++) {
                w0[k] = v0 ? __ldg(Wd + (size_t)k * NPC + c0) : 0.f;
                w1[k] = v1 ? __ldg(Wd + (size_t)k * NPC + c1) : 0.f;
            }
#pragma unroll
            for (int s = 0; s < SCH; s++) {
                float4 x = *(const float4*)&Xs[s][dq];
                acc0[s] += x.x * w0[0]; acc1[s] += x.x * w1[0];
                acc0[s] += x.y * w0[1]; acc1[s] += x.y * w1[1];
                acc0[s] += x.z * w0[2]; acc1[s] += x.z * w1[2];
                acc0[s] += x.w * w0[3]; acc1[s] += x.w * w1[3];
            }
        }

        for (int s = 0; s < ns; s++) {
            int sid = ids[s];
            if (v0) atomicAdd(&g_bot_logits[sid * NPC + c0], acc0[s]);
            if (v1) atomicAdd(&g_bot_logits[sid * NPC + c1], acc1[s]);
        }
    }
}

// ---------------- 4: fused finish — both softmaxes + output ------------------
// one warp per sample
__global__ void __launch_bounds__(256) k_finish(
    const float* __restrict__ bt,   // [224]
    const float* __restrict__ bb,   // [NCLASSES, NPC]
    float* __restrict__ out)
{
    int sid  = (blockIdx.x * blockDim.x + threadIdx.x) >> 5;
    int lane = threadIdx.x & 31;
    if (sid >= BATCH) return;
    int c = g_pos_top[sid];

    // ---- top softmax over 224 classes (7 per lane) ----
    float lt[7];
    float mx = -CUDART_INF_F;
#pragma unroll
    for (int i = 0; i < 7; i++) {
        int cc = lane + 32 * i;
        lt[i] = g_top_logits[sid * NCLASSES + cc] + bt[cc];
        mx = fmaxf(mx, lt[i]);
    }
#pragma unroll
    for (int o = 16; o > 0; o >>= 1) mx = fmaxf(mx, __shfl_xor_sync(0xFFFFFFFFu, mx, o));
    float s = 0.f;
#pragma unroll
    for (int i = 0; i < 7; i++) s += __expf(lt[i] - mx);
#pragma unroll
    for (int o = 16; o > 0; o >>= 1) s += __shfl_xor_sync(0xFFFFFFFFu, s, o);

    float myv  = lt[c >> 5];
    float tgt  = __shfl_sync(0xFFFFFFFFu, myv, c & 31);
    float top_p = __expf(tgt - mx) / s;

    // ---- bottom softmax over 225 columns (8 per lane, last partial) ----
    float vb[8];
    float mxb = -CUDART_INF_F;
#pragma unroll
    for (int k = 0; k < 8; k++) {
        int col = lane + 32 * k;
        if (col < NPC) {
            vb[k] = g_bot_logits[sid * NPC + col] + bb[c * NPC + col];
            mxb = fmaxf(mxb, vb[k]);
        } else vb[k] = -CUDART_INF_F;
    }
#pragma unroll
    for (int o = 16; o > 0; o >>= 1) mxb = fmaxf(mxb, __shfl_xor_sync(0xFFFFFFFFu, mxb, o));
    float sb = 0.f;
#pragma unroll
    for (int k = 0; k < 8; k++) sb += __expf(vb[k] - mxb);
#pragma unroll
    for (int o = 16; o > 0; o >>= 1) sb += __shfl_xor_sync(0xFFFFFFFFu, sb, o);

    int pb = g_pos_bottom[sid];
    if (lane == (pb & 31))
        out[sid] = top_p * (__expf(vb[pb >> 5] - mxb) / sb);
}

// ---------------- launch -----------------------------------------------------
extern "C" void kernel_launch(void* const* d_in, const int* in_sizes, int n_in,
                              void* d_out, int out_size)
{
    const float* X   = (const float*)d_in[0];   // [1024, 1024]
    const void*  lab = d_in[1];                 // [1024] int32/int64
    const float* Wt  = (const float*)d_in[2];   // [1024, 224]
    const float* bt  = (const float*)d_in[3];   // [224]
    const float* Wb  = (const float*)d_in[4];   // [224, 1024, 225]
    const float* bb  = (const float*)d_in[5];   // [224, 225]
    float* out = (float*)d_out;

    k_zero<<<448, 256>>>();
    k_prep<<<1, 1024>>>(lab);
    k_top<<<dim3(BATCH / TROWS, KSEG), 256>>>(X, Wt);
    k_bottom<<<dim3(NCLASSES, DSEG), 128>>>(X, Wb);
    k_finish<<<BATCH / 8, 256>>>(bt, bb, out);
}

// round 5
// speedup vs baseline: 3.8327x; 1.0097x over previous
#include <cuda_runtime.h>
#include <cuda_bf16.h>
#include <math_constants.h>

#define BATCH    1024
#define NHID     1024
#define NCLASSES 224
#define NPC      225
#define DSEG     8
#define DLEN     128      // NHID / DSEG
#define SCH      8        // samples per chunk (bottom)
#define KSEG     8        // split-K for top gemm
#define KLEN     128      // NHID / KSEG
#define TROWS    64       // rows per top-gemm block (8 warps x 8 rows)

// ---------------- scratch (device globals) ----------------------------------
__device__ float g_top_logits[BATCH * NCLASSES];
__device__ float g_bot_logits[BATCH * NPC];
__device__ int   g_pos_top[BATCH];
__device__ int   g_pos_bottom[BATCH];
__device__ int   g_count[NCLASSES];
__device__ int   g_offset[NCLASSES + 1];
__device__ int   g_sorted[BATCH];

// ---------------- 0: zero logit accumulators ---------------------------------
__global__ void __launch_bounds__(256) k_zero()
{
    int i = blockIdx.x * blockDim.x + threadIdx.x;
    int N1 = BATCH * NCLASSES;          // 229376
    int N2 = BATCH * NPC;               // 230400
    int stride = gridDim.x * blockDim.x;
    for (int j = i; j < N1; j += stride) g_top_logits[j] = 0.f;
    for (int j = i; j < N2; j += stride) g_bot_logits[j] = 0.f;
}

// ---------------- 1: prep — decode labels, histogram, scan, scatter ---------
__global__ void __launch_bounds__(1024) k_prep(const void* __restrict__ labels_raw)
{
    __shared__ int s_count[NCLASSES];
    __shared__ int s_off[NCLASSES];
    int t = threadIdx.x;   // 1024 threads, one per sample

    if (t < NCLASSES) s_count[t] = 0;
    __syncthreads();

    // detect int64 vs int32 labels (odd 32-bit words all zero => int64 LE)
    const unsigned int* w = (const unsigned int*)labels_raw;
    bool is64 = ((w[1] | w[3] | w[5] | w[7] | w[9] | w[11] | w[13] | w[15]) == 0u);
    long long lab = is64 ? ((const long long*)labels_raw)[t]
                         : (long long)(((const int*)labels_raw)[t]);
    int pt = (int)(lab / NPC);
    int pb = (int)(lab % NPC);
    g_pos_top[t]    = pt;
    g_pos_bottom[t] = pb;
    atomicAdd(&s_count[pt], 1);
    __syncthreads();

    // warp 0: exclusive scan of 224 counts
    if (t < 32) {
        int base = t * 7;
        int v[7], loc[7];
        int sum = 0;
#pragma unroll
        for (int i = 0; i < 7; i++) v[i] = s_count[base + i];
#pragma unroll
        for (int i = 0; i < 7; i++) { loc[i] = sum; sum += v[i]; }
        int run = sum;
#pragma unroll
        for (int o = 1; o < 32; o <<= 1) {
            int nb = __shfl_up_sync(0xFFFFFFFFu, run, o);
            if (t >= o) run += nb;
        }
        int excl = run - sum;
#pragma unroll
        for (int i = 0; i < 7; i++) {
            s_off[base + i]    = excl + loc[i];
            g_offset[base + i] = excl + loc[i];
        }
        if (t == 31) g_offset[NCLASSES] = excl + sum;
    }
    __syncthreads();
    if (t < NCLASSES) g_count[t] = s_count[t];

    int p = atomicAdd(&s_off[pt], 1);
    g_sorted[p] = t;
}

// ---------------- 2: top GEMM (split-K, atomic epilogue) ----------------------
// grid (16 rowgroups, 8 ksegs) = 128 blocks (one wave); 8 warps x 8 rows each.
__global__ void __launch_bounds__(256) k_top(
    const float* __restrict__ X,
    const float* __restrict__ Wt)    // [NHID, NCLASSES]
{
    int r0 = blockIdx.x * TROWS;
    int k0 = blockIdx.y * KLEN;
    int t = threadIdx.x, warp = t >> 5, lane = t & 31;

    __shared__ float Xs[TROWS][KLEN];      // 32 KB
    __shared__ float Ws[16][NCLASSES];     // 14.3 KB

    // stage X tile (64 rows x 128 k), float4 coalesced
    for (int i = t; i < TROWS * 32; i += 256) {
        int r = i >> 5, q = i & 31;
        const float4* src = (const float4*)(X + (size_t)(r0 + r) * NHID + k0);
        ((float4*)&Xs[r][0])[q] = src[q];
    }

    float acc[8][7];
#pragma unroll
    for (int r = 0; r < 8; r++)
#pragma unroll
        for (int i = 0; i < 7; i++) acc[r][i] = 0.f;

    for (int kc = 0; kc < KLEN; kc += 16) {
        __syncthreads();
        for (int i = t; i < 16 * NCLASSES; i += 256) {
            int kk = i / NCLASSES;
            int c  = i - kk * NCLASSES;
            Ws[kk][c] = Wt[(size_t)(k0 + kc + kk) * NCLASSES + c];
        }
        __syncthreads();
#pragma unroll
        for (int kq = 0; kq < 16; kq += 4) {
            // broadcast X values via LDS.128 (4 k per wavefront per row)
            float4 xv[8];
#pragma unroll
            for (int r = 0; r < 8; r++)
                xv[r] = *(const float4*)&Xs[warp * 8 + r][kc + kq];
            const float* xf = (const float*)xv;
#pragma unroll
            for (int j = 0; j < 4; j++) {
#pragma unroll
                for (int i = 0; i < 7; i++) {
                    float wv = Ws[kq + j][lane + 32 * i];
#pragma unroll
                    for (int r = 0; r < 8; r++)
                        acc[r][i] += xf[r * 4 + j] * wv;
                }
            }
        }
    }

#pragma unroll
    for (int r = 0; r < 8; r++) {
        int row = r0 + warp * 8 + r;
#pragma unroll
        for (int i = 0; i < 7; i++)
            atomicAdd(&g_top_logits[row * NCLASSES + lane + 32 * i], acc[r][i]);
    }
}

// ---------------- 3: bottom split-D (2 cols/thread, LDS.128 X) ---------------
// grid (224 classes, 8 d-segments); block 128 = 4 warps; warp w covers cols
// [64w, 64w+64): lane l owns cols 64w+l and 64w+32+l.
__global__ void __launch_bounds__(128) k_bottom(
    const float* __restrict__ X,
    const float* __restrict__ Wb)    // [NCLASSES, NHID, NPC]
{
    int c   = blockIdx.x;
    int seg = blockIdx.y;
    int n = g_count[c];
    if (n == 0) return;
    int base = g_offset[c];
    int d0   = seg * DLEN;
    int t = threadIdx.x, warp = t >> 5, lane = t & 31;

    int c0 = warp * 64 + lane;
    int c1 = c0 + 32;
    bool v0 = (c0 < NPC), v1 = (c1 < NPC);

    __shared__ float Xs[SCH][DLEN];    // 4 KB
    __shared__ int   ids[SCH];

    const float* W = Wb + (size_t)c * NHID * NPC + (size_t)d0 * NPC;

    for (int s0 = 0; s0 < n; s0 += SCH) {
        int ns = min(SCH, n - s0);
        __syncthreads();
        if (t < ns) ids[t] = g_sorted[base + s0 + t];
        __syncthreads();

        // stage X rows (float4 coalesced), zero-fill unused sample slots
        for (int i = t; i < SCH * 32; i += 128) {
            int s = i >> 5, q = i & 31;
            float4 val = make_float4(0.f, 0.f, 0.f, 0.f);
            if (s < ns)
                val = ((const float4*)(X + (size_t)ids[s] * NHID + d0))[q];
            ((float4*)&Xs[s][0])[q] = val;
        }
        __syncthreads();

        float acc0[SCH], acc1[SCH];
#pragma unroll
        for (int s = 0; s < SCH; s++) { acc0[s] = 0.f; acc1[s] = 0.f; }

#pragma unroll 2
        for (int dq = 0; dq < DLEN; dq += 4) {
            float w0[4], w1[4];
            const float* Wd = W + (size_t)dq * NPC;
#pragma unroll
            for (int k = 0; k < 4; k++) {
                w0[k] = v0 ? __ldg(Wd + (size_t)k * NPC + c0) : 0.f;
                w1[k] = v1 ? __ldg(Wd + (size_t)k * NPC + c1) : 0.f;
            }
#pragma unroll
            for (int s = 0; s < SCH; s++) {
                float4 x = *(const float4*)&Xs[s][dq];
                acc0[s] += x.x * w0[0]; acc1[s] += x.x * w1[0];
                acc0[s] += x.y * w0[1]; acc1[s] += x.y * w1[1];
                acc0[s] += x.z * w0[2]; acc1[s] += x.z * w1[2];
                acc0[s] += x.w * w0[3]; acc1[s] += x.w * w1[3];
            }
        }

        for (int s = 0; s < ns; s++) {
            int sid = ids[s];
            if (v0) atomicAdd(&g_bot_logits[sid * NPC + c0], acc0[s]);
            if (v1) atomicAdd(&g_bot_logits[sid * NPC + c1], acc1[s]);
        }
    }
}

// ---------------- 4: fused finish — both softmaxes + output ------------------
// one warp per sample
__global__ void __launch_bounds__(256) k_finish(
    const float* __restrict__ bt,   // [224]
    const float* __restrict__ bb,   // [NCLASSES, NPC]
    float* __restrict__ out)
{
    int sid  = (blockIdx.x * blockDim.x + threadIdx.x) >> 5;
    int lane = threadIdx.x & 31;
    if (sid >= BATCH) return;
    int c = g_pos_top[sid];

    // ---- top softmax over 224 classes (7 per lane) ----
    float lt[7];
    float mx = -CUDART_INF_F;
#pragma unroll
    for (int i = 0; i < 7; i++) {
        int cc = lane + 32 * i;
        lt[i] = g_top_logits[sid * NCLASSES + cc] + bt[cc];
        mx = fmaxf(mx, lt[i]);
    }
#pragma unroll
    for (int o = 16; o > 0; o >>= 1) mx = fmaxf(mx, __shfl_xor_sync(0xFFFFFFFFu, mx, o));
    float s = 0.f;
#pragma unroll
    for (int i = 0; i < 7; i++) s += __expf(lt[i] - mx);
#pragma unroll
    for (int o = 16; o > 0; o >>= 1) s += __shfl_xor_sync(0xFFFFFFFFu, s, o);

    float myv  = lt[c >> 5];
    float tgt  = __shfl_sync(0xFFFFFFFFu, myv, c & 31);
    float top_p = __expf(tgt - mx) / s;

    // ---- bottom softmax over 225 columns (8 per lane, last partial) ----
    float vb[8];
    float mxb = -CUDART_INF_F;
#pragma unroll
    for (int k = 0; k < 8; k++) {
        int col = lane + 32 * k;
        if (col < NPC) {
            vb[k] = g_bot_logits[sid * NPC + col] + bb[c * NPC + col];
            mxb = fmaxf(mxb, vb[k]);
        } else vb[k] = -CUDART_INF_F;
    }
#pragma unroll
    for (int o = 16; o > 0; o >>= 1) mxb = fmaxf(mxb, __shfl_xor_sync(0xFFFFFFFFu, mxb, o));
    float sb = 0.f;
#pragma unroll
    for (int k = 0; k < 8; k++) sb += __expf(vb[k] - mxb);
#pragma unroll
    for (int o = 16; o > 0; o >>= 1) sb += __shfl_xor_sync(0xFFFFFFFFu, sb, o);

    int pb = g_pos_bottom[sid];
    if (lane == (pb & 31))
        out[sid] = top_p * (__expf(vb[pb >> 5] - mxb) / sb);
}

// ---------------- launch -----------------------------------------------------
extern "C" void kernel_launch(void* const* d_in, const int* in_sizes, int n_in,
                              void* d_out, int out_size)
{
    const float* X   = (const float*)d_in[0];   // [1024, 1024]
    const void*  lab = d_in[1];                 // [1024] int32/int64
    const float* Wt  = (const float*)d_in[2];   // [1024, 224]
    const float* bt  = (const float*)d_in[3];   // [224]
    const float* Wb  = (const float*)d_in[4];   // [224, 1024, 225]
    const float* bb  = (const float*)d_in[5];   // [224, 225]
    float* out = (float*)d_out;

    k_zero<<<448, 256>>>();
    k_prep<<<1, 1024>>>(lab);
    k_top<<<dim3(BATCH / TROWS, KSEG), 256>>>(X, Wt);
    k_bottom<<<dim3(NCLASSES, DSEG), 128>>>(X, Wb);
    k_finish<<<BATCH / 8, 256>>>(bt, bb, out);
}